// round 13
// baseline (speedup 1.0000x reference)
#include <cuda_runtime.h>
#include <cstdint>

#define Bn 16
#define TNEW 8
#define Cdim 1024
#define Hn 16
#define HD 64
#define TPAST 4096
#define TFULL 4104
#define BHN 256     // Bn*Hn
#define NTOK 128    // Bn*TNEW
#define KSQ 8       // QKV GEMM K-split (KC = 128)
#define KSP 16      // proj GEMM K-split (KC = 64)
#define ASPLIT 2    // attention key-split (512 blocks = ONE wave at 4/SM)
#define NCH 32      // 64-key chunks per attention block

// scratch (no cudaMalloc allowed)
__device__ __align__(16) float g_qkv[NTOK * 3 * Cdim];        // 1.5 MB
__device__ __align__(16) float g_y[NTOK * Cdim];              // 512 KB
__device__ __align__(16) float g_part[KSQ * 128 * 3072];      // 12.6 MB
__device__ float g_pm[BHN * ASPLIT * 8];
__device__ float g_pl[BHN * ASPLIT * 8];
__device__ __align__(16) float g_po[BHN * ASPLIT * 8 * 64];   // 1 MB

__device__ __forceinline__ uint32_t smem_u32(const void* p) {
    return (uint32_t)__cvta_generic_to_shared(p);
}
__device__ __forceinline__ void cp16(uint32_t dst, const void* src) {
    asm volatile("cp.async.cg.shared.global [%0], [%1], 16;\n" :: "r"(dst), "l"(src));
}
__device__ __forceinline__ void cp_commit() {
    asm volatile("cp.async.commit_group;\n");
}
template <int N>
__device__ __forceinline__ void cp_wait() {
    asm volatile("cp.async.wait_group %0;\n" :: "n"(N));
}

// ---------------------------------------------------------------------------
// tf32 split-MMA GEMM (Markidis 2-term split -> fp32-class accuracy).
// part[ks][m][n] = sum_{k in chunk} A[m][k]*Bw[n][k].  M fixed = 128.
// Block tile: 128m x 64n, 256 threads (8 warps as 4m x 2n), staged 32-k chunks.
// (R11-exact: this configuration measured 220.4us total.)
// ---------------------------------------------------------------------------
__device__ __forceinline__ void tf32_split(float a, uint32_t& hi, uint32_t& lo) {
    uint32_t h;
    asm("cvt.rna.tf32.f32 %0, %1;" : "=r"(h) : "f"(a));
    float r = a - __uint_as_float(h);
    uint32_t l;
    asm("cvt.rna.tf32.f32 %0, %1;" : "=r"(l) : "f"(r));
    hi = h; lo = l;
}

__device__ __forceinline__ void mma_tf32(float* d, const uint32_t* a, const uint32_t* b) {
    asm volatile(
        "mma.sync.aligned.m16n8k8.row.col.f32.tf32.tf32.f32 "
        "{%0,%1,%2,%3}, {%4,%5,%6,%7}, {%8,%9}, {%0,%1,%2,%3};\n"
        : "+f"(d[0]), "+f"(d[1]), "+f"(d[2]), "+f"(d[3])
        : "r"(a[0]), "r"(a[1]), "r"(a[2]), "r"(a[3]), "r"(b[0]), "r"(b[1]));
}

__global__ void __launch_bounds__(256) gemm_mma_splitk(
    const float* __restrict__ A, const float* __restrict__ Bw,
    float* __restrict__ part, int N, int K, int KC)
{
    __shared__ float As[128][36];   // pad 36: conflict-free fragment gathers
    __shared__ float Ws[64][36];

    int n0 = blockIdx.x * 64;
    int kbase = blockIdx.y * KC;
    int t = threadIdx.x, lane = t & 31, wid = t >> 5;
    int grp = lane >> 2, tig = lane & 3;
    int wm = (wid >> 1) * 32;       // warp m offset (4 warps over 128m)
    int wn = (wid & 1) * 32;        // warp n offset (2 warps over 64n)

    float d[2][4][4];
    #pragma unroll
    for (int i = 0; i < 2; i++)
        #pragma unroll
        for (int j = 0; j < 4; j++)
            #pragma unroll
            for (int r = 0; r < 4; r++) d[i][j][r] = 0.f;

    for (int kk = 0; kk < KC; kk += 32) {
        // stage A 128x32
        #pragma unroll
        for (int it = 0; it < 4; it++) {
            int idx = t + it * 256;         // 0..1023
            int row = idx >> 3, c4 = (idx & 7) * 4;
            float4 v = *(const float4*)&A[(size_t)row * K + kbase + kk + c4];
            As[row][c4] = v.x; As[row][c4 + 1] = v.y;
            As[row][c4 + 2] = v.z; As[row][c4 + 3] = v.w;
        }
        // stage W 64x32
        #pragma unroll
        for (int it = 0; it < 2; it++) {
            int idx = t + it * 256;         // 0..511
            int row = idx >> 3, c4 = (idx & 7) * 4;
            float4 v = *(const float4*)&Bw[(size_t)(n0 + row) * K + kbase + kk + c4];
            Ws[row][c4] = v.x; Ws[row][c4 + 1] = v.y;
            Ws[row][c4 + 2] = v.z; Ws[row][c4 + 3] = v.w;
        }
        __syncthreads();

        #pragma unroll
        for (int ks = 0; ks < 4; ks++) {
            int kb = ks * 8;
            uint32_t ah[2][4], al[2][4];
            #pragma unroll
            for (int i = 0; i < 2; i++) {
                int mb = wm + i * 16;
                tf32_split(As[mb + grp][kb + tig],         ah[i][0], al[i][0]);
                tf32_split(As[mb + grp + 8][kb + tig],     ah[i][1], al[i][1]);
                tf32_split(As[mb + grp][kb + tig + 4],     ah[i][2], al[i][2]);
                tf32_split(As[mb + grp + 8][kb + tig + 4], ah[i][3], al[i][3]);
            }
            uint32_t bh[4][2], bl[4][2];
            #pragma unroll
            for (int j = 0; j < 4; j++) {
                int nb = wn + j * 8;
                tf32_split(Ws[nb + grp][kb + tig],     bh[j][0], bl[j][0]);
                tf32_split(Ws[nb + grp][kb + tig + 4], bh[j][1], bl[j][1]);
            }
            #pragma unroll
            for (int i = 0; i < 2; i++)
                #pragma unroll
                for (int j = 0; j < 4; j++) {
                    mma_tf32(d[i][j], ah[i], bh[j]);   // hi*hi
                    mma_tf32(d[i][j], ah[i], bl[j]);   // hi*lo
                    mma_tf32(d[i][j], al[i], bh[j]);   // lo*hi
                }
        }
        __syncthreads();
    }

    // epilogue: write partials (fragment layout -> (m, n) coords)
    float* pout = part + (size_t)blockIdx.y * 128 * N;
    #pragma unroll
    for (int i = 0; i < 2; i++) {
        #pragma unroll
        for (int j = 0; j < 4; j++) {
            int m = wm + i * 16 + grp;
            int n = n0 + wn + j * 8 + tig * 2;
            *(float2*)&pout[(size_t)m * N + n]       = make_float2(d[i][j][0], d[i][j][1]);
            *(float2*)&pout[(size_t)(m + 8) * N + n] = make_float2(d[i][j][2], d[i][j][3]);
        }
    }
}

// reduce QKV partials + bias -> g_qkv, AND scatter new k/v rows into caches
__global__ void __launch_bounds__(256) reduce_qkv(
    const float* __restrict__ part, const float* __restrict__ bias,
    float* __restrict__ out, float* __restrict__ kout, float* __restrict__ vout)
{
    int idx = blockIdx.x * 256 + threadIdx.x;   // 128 * 768
    int m = idx / 768, n = idx % 768;
    float4 s = *(const float4*)&bias[n * 4];
    #pragma unroll
    for (int ks = 0; ks < KSQ; ks++) {
        float4 p = *(const float4*)&part[((size_t)ks * 128 + m) * 3072 + n * 4];
        s.x += p.x; s.y += p.y; s.z += p.z; s.w += p.w;
    }
    *(float4*)&out[(size_t)m * 3072 + n * 4] = s;

    int c = n * 4;
    if (c >= 1024) {
        int isv = c >= 2048;
        int cc = c - (isv ? 2048 : 1024);
        int hh = cc >> 6, d = cc & 63;
        int bb = m >> 3, j = m & 7;
        float* dst = isv ? vout : kout;
        *(float4*)&dst[(((size_t)(bb * 16 + hh)) * TFULL + TPAST + j) * 64 + d] = s;
    }
}

// reduce projection partials + bias -> out
__global__ void __launch_bounds__(256) reduce_proj(
    const float* __restrict__ part, const float* __restrict__ bias,
    float* __restrict__ out)
{
    int idx = blockIdx.x * 256 + threadIdx.x;   // 128 * 256
    int m = idx >> 8, n = idx & 255;
    float4 s = *(const float4*)&bias[n * 4];
    #pragma unroll
    for (int ks = 0; ks < KSP; ks++) {
        float4 p = *(const float4*)&part[((size_t)ks * 128 + m) * 1024 + n * 4];
        s.x += p.x; s.y += p.y; s.z += p.z; s.w += p.w;
    }
    *(float4*)&out[(size_t)m * 1024 + n * 4] = s;
}

// ---------------------------------------------------------------------------
// Pipelined split attention.  grid (BHN, ASPLIT=2) = 512 blocks = ONE wave.
// 64-key chunks; k double-buffered cp.async; v single-buffered deferred;
// fused cache copy.  55.9KB smem -> 4 blocks/SM.
// ---------------------------------------------------------------------------
__device__ __forceinline__ void softmax_update10(
    float* Ss, float* m_s, float* l_s, float* f_s, int lane, int wid)
{
    int j = wid;                       // warp w owns query row j=w
    float v0 = Ss[lane * 10 + j];
    float v1 = Ss[(lane + 32) * 10 + j];
    float mx = fmaxf(v0, v1);
    #pragma unroll
    for (int o = 16; o; o >>= 1) mx = fmaxf(mx, __shfl_xor_sync(0xffffffffu, mx, o));
    float m_old = m_s[j];
    float m_new = fmaxf(m_old, mx);
    float p0 = __expf(v0 - m_new);
    float p1 = __expf(v1 - m_new);
    Ss[lane * 10 + j] = p0;
    Ss[(lane + 32) * 10 + j] = p1;
    float sum = p0 + p1;
    #pragma unroll
    for (int o = 16; o; o >>= 1) sum += __shfl_xor_sync(0xffffffffu, sum, o);
    if (lane == 0) {
        float f = __expf(m_old - m_new);
        l_s[j] = l_s[j] * f + sum;
        m_s[j] = m_new;
        f_s[j] = f;
    }
}

// dynamic smem layout (bytes):
//   qs: 0..2048 | k_sm: 2048..34816 (2x) | v_sm: 34816..51200 (1x)
//   Ss: 51200..53760 | m/l/f: 53760..53856 | red: 53856..55904
#define ATTN_SMEM 55904

__global__ void __launch_bounds__(256, 4) attn_split(
    const float* __restrict__ past_k, const float* __restrict__ past_v,
    float* __restrict__ kout, float* __restrict__ vout)
{
    extern __shared__ char smraw[];
    float*  qs   = (float*)smraw;
    float4* k_sm = (float4*)(smraw + 2048);
    float4* v_sm = (float4*)(smraw + 34816);
    float*  Ss   = (float*)(smraw + 51200);
    float*  m_s  = (float*)(smraw + 53760);
    float*  l_s  = m_s + 8;
    float*  f_s  = m_s + 16;
    float4* red  = (float4*)(smraw + 53856);

    int bh = blockIdx.x;
    int s  = blockIdx.y;
    int b = bh >> 4, h = bh & 15;
    int t = threadIdx.x, lane = t & 31, wid = t >> 5;

    // load q (scale folded: 1/sqrt(64) = 0.125)
    for (int i = t; i < 512; i += 256) {
        int j = i >> 6, d = i & 63;
        qs[i] = g_qkv[(size_t)(b * 8 + j) * 3072 + h * 64 + d] * 0.125f;
    }
    if (t < 8) { m_s[t] = -3.0e38f; l_s[t] = 0.f; }

    const float4* ksrc = (const float4*)past_k + (size_t)bh * TPAST * 16;
    const float4* vsrc = (const float4*)past_v + (size_t)bh * TPAST * 16;
    float4* kdst = (float4*)kout + (size_t)bh * TFULL * 16;
    float4* vdst = (float4*)vout + (size_t)bh * TFULL * 16;
    const float4* q4 = (const float4*)qs;
    const float2* v2s = (const float2*)v_sm;

    const int ld_r = t >> 4, ld_d4 = t & 15;
    uint32_t k_b0 = smem_u32(k_sm), v_b0 = smem_u32(v_sm);

    const int j2 = (wid & 3) * 2;
    const int r_sc = (wid >> 2) * 32 + lane;
    const int jp = t >> 6;
    const int rh = (t >> 5) & 1;
    const int d2 = lane;

    float accA0 = 0.f, accA1 = 0.f, accB0 = 0.f, accB1 = 0.f;

    const int c_begin = s * (TPAST / ASPLIT);

    // prefetch k chunk 0
    #pragma unroll
    for (int it = 0; it < 4; it++) {
        int r = ld_r + it * 16;
        int sw = r * 16 + (ld_d4 ^ (r & 15));
        cp16(k_b0 + (uint32_t)sw * 16, ksrc + (size_t)(c_begin + r) * 16 + ld_d4);
    }
    cp_commit();

    for (int ci = 0; ci < NCH; ci++) {
        int c0 = c_begin + ci * 64;
        int buf = ci & 1;
        cp_wait<0>();          // only k(ci) outstanding here
        __syncthreads();       // sync_a: k(ci) visible; accum(ci-1) done

        // issue v(ci) into the single v buffer (now safe to overwrite)
        #pragma unroll
        for (int it = 0; it < 4; it++) {
            int r = ld_r + it * 16;
            int sw = r * 16 + (ld_d4 ^ (r & 15));
            cp16(v_b0 + (uint32_t)sw * 16, vsrc + (size_t)(c0 + r) * 16 + ld_d4);
        }
        cp_commit();

        bool more = (ci + 1 < NCH);
        if (more) {            // prefetch k(ci+1) into the other k buffer
            uint32_t kb = k_b0 + (uint32_t)(buf ^ 1) * 16384;
            #pragma unroll
            for (int it = 0; it < 4; it++) {
                int r = ld_r + it * 16;
                int sw = r * 16 + (ld_d4 ^ (r & 15));
                cp16(kb + (uint32_t)sw * 16, ksrc + (size_t)(c0 + 64 + r) * 16 + ld_d4);
            }
            cp_commit();
        }

        const float4* kbp = k_sm + buf * 1024;

        // ---- copy k chunk to cache (streaming STG from smem) ----
        #pragma unroll
        for (int it = 0; it < 4; it++) {
            int r = ld_r + it * 16;
            int sw = r * 16 + (ld_d4 ^ (r & 15));
            __stcs(&kdst[(size_t)(c0 + r) * 16 + ld_d4], kbp[sw]);
        }

        // ---- scores: warp-uniform q (broadcast LDS), per-lane key ----
        {
            int r = r_sc;
            float s0 = 0.f, s1 = 0.f;
            #pragma unroll
            for (int d4 = 0; d4 < 16; d4++) {
                float4 kv = kbp[r * 16 + (d4 ^ (r & 15))];
                float4 qa = q4[j2 * 16 + d4];
                float4 qb = q4[(j2 + 1) * 16 + d4];
                s0 += kv.x * qa.x + kv.y * qa.y + kv.z * qa.z + kv.w * qa.w;
                s1 += kv.x * qb.x + kv.y * qb.y + kv.z * qb.z + kv.w * qb.w;
            }
            Ss[r * 10 + j2]     = s0;
            Ss[r * 10 + j2 + 1] = s1;
        }
        __syncthreads();       // sync_b: scores written
        softmax_update10(Ss, m_s, l_s, f_s, lane, wid);
        if (more) cp_wait<1>(); else cp_wait<0>();   // v(ci) arrived
        __syncthreads();       // sync_c: p, f, and v visible

        {
            float f0 = f_s[2 * jp], f1 = f_s[2 * jp + 1];
            accA0 *= f0; accA1 *= f0; accB0 *= f1; accB1 *= f1;
        }
        // ---- copy v chunk to cache ----
        #pragma unroll
        for (int it = 0; it < 4; it++) {
            int r = ld_r + it * 16;
            int sw = r * 16 + (ld_d4 ^ (r & 15));
            __stcs(&vdst[(size_t)(c0 + r) * 16 + ld_d4], v_sm[sw]);
        }
        // ---- accumulate: p pair broadcast, v float2 shared by 2 queries ----
        {
            int d4 = d2 >> 1, dlo = d2 & 1;
            #pragma unroll 8
            for (int rr = 0; rr < 32; rr++) {
                int r = rh * 32 + rr;
                float2 p = *(const float2*)&Ss[r * 10 + 2 * jp];
                float2 vv = v2s[(r * 16 + (d4 ^ (r & 15))) * 2 + dlo];
                accA0 += p.x * vv.x; accA1 += p.x * vv.y;
                accB0 += p.y * vv.x; accB1 += p.y * vv.y;
            }
        }
        // no trailing sync: next iteration's sync_a orders accum vs reuse
    }
    __syncthreads();           // protect k_sm/v_sm before tail reuse

    // =================== last split: 8 new keys (causal mask) ==============
    if (s == ASPLIT - 1) {
        if (t < 128) {
            int r = t >> 4, d4 = t & 15;
            k_sm[r * 16 + (d4 ^ (r & 15))] = kdst[(size_t)(TPAST + r) * 16 + d4];
        } else {
            int tt = t - 128;
            int r = tt >> 4, d4 = tt & 15;
            v_sm[r * 16 + (d4 ^ (r & 15))] = vdst[(size_t)(TPAST + r) * 16 + d4];
        }
        __syncthreads();
        {
            int r = r_sc;
            float s0 = -3.0e38f, s1 = -3.0e38f;
            if (r < 8) {
                float a0 = 0.f, a1 = 0.f;
                #pragma unroll
                for (int d4 = 0; d4 < 16; d4++) {
                    float4 kv = k_sm[r * 16 + (d4 ^ (r & 15))];
                    float4 qa = q4[j2 * 16 + d4];
                    float4 qb = q4[(j2 + 1) * 16 + d4];
                    a0 += kv.x * qa.x + kv.y * qa.y + kv.z * qa.z + kv.w * qa.w;
                    a1 += kv.x * qb.x + kv.y * qb.y + kv.z * qb.z + kv.w * qb.w;
                }
                if (r <= j2)     s0 = a0;
                if (r <= j2 + 1) s1 = a1;
            }
            Ss[r * 10 + j2]     = s0;
            Ss[r * 10 + j2 + 1] = s1;
        }
        __syncthreads();
        softmax_update10(Ss, m_s, l_s, f_s, lane, wid);
        __syncthreads();
        {
            float f0 = f_s[2 * jp], f1 = f_s[2 * jp + 1];
            accA0 *= f0; accA1 *= f0; accB0 *= f1; accB1 *= f1;
        }
        if (rh == 0) {
            int d4 = d2 >> 1, dlo = d2 & 1;
            #pragma unroll
            for (int r = 0; r < 8; r++) {
                float2 p = *(const float2*)&Ss[r * 10 + 2 * jp];
                float2 vv = v2s[(r * 16 + (d4 ^ (r & 15))) * 2 + dlo];
                accA0 += p.x * vv.x; accA1 += p.x * vv.y;
                accB0 += p.y * vv.x; accB1 += p.y * vv.y;
            }
        }
        __syncthreads();
    }

    // cross-half reduce + store partials
    if (rh == 1) red[jp * 32 + d2] = make_float4(accA0, accA1, accB0, accB1);
    __syncthreads();
    if (rh == 0) {
        float4 o = red[jp * 32 + d2];
        accA0 += o.x; accA1 += o.y; accB0 += o.z; accB1 += o.w;
        int j0 = 2 * jp, j1 = 2 * jp + 1;
        size_t base = (size_t)(bh * ASPLIT + s) * 8;
        g_po[(base + j0) * 64 + 2 * d2]     = accA0;
        g_po[(base + j0) * 64 + 2 * d2 + 1] = accA1;
        g_po[(base + j1) * 64 + 2 * d2]     = accB0;
        g_po[(base + j1) * 64 + 2 * d2 + 1] = accB1;
    }
    if (t < 8) {
        g_pm[(bh * ASPLIT + s) * 8 + t] = m_s[t];
        g_pl[(bh * ASPLIT + s) * 8 + t] = l_s[t];
    }
}

// combine split partials -> g_y (token-major for projection GEMM)
__global__ void __launch_bounds__(512) attn_combine()
{
    int bh = blockIdx.x;
    int b = bh >> 4, h = bh & 15;
    int t = threadIdx.x;
    int j = t >> 6, d = t & 63;

    float mm[ASPLIT], ll[ASPLIT];
    float m_g = -3.0e38f;
    #pragma unroll
    for (int s = 0; s < ASPLIT; s++) {
        mm[s] = g_pm[(bh * ASPLIT + s) * 8 + j];
        ll[s] = g_pl[(bh * ASPLIT + s) * 8 + j];
        m_g = fmaxf(m_g, mm[s]);
    }
    float l_g = 0.f, o = 0.f;
    #pragma unroll
    for (int s = 0; s < ASPLIT; s++) {
        float w = __expf(mm[s] - m_g);
        l_g += ll[s] * w;
        o += g_po[((size_t)(bh * ASPLIT + s) * 8 + j) * 64 + d] * w;
    }
    g_y[(size_t)(b * 8 + j) * Cdim + h * 64 + d] = o / l_g;
}

// ---------------------------------------------------------------------------
// kernel_launch (single stream):
//   gemm_mma(qkv) -> reduce_qkv(+scatter) -> attn_split -> attn_combine
//   -> gemm_mma(proj) -> reduce_proj
// ---------------------------------------------------------------------------
extern "C" void kernel_launch(void* const* d_in, const int* in_sizes, int n_in,
                              void* d_out, int out_size)
{
    const float* x      = (const float*)d_in[0];
    const float* past_k = (const float*)d_in[1];
    const float* past_v = (const float*)d_in[2];
    const float* W_attn = (const float*)d_in[3];
    const float* b_attn = (const float*)d_in[4];
    const float* W_proj = (const float*)d_in[5];
    const float* b_proj = (const float*)d_in[6];

    float* out  = (float*)d_out;
    float* kout = out + (size_t)NTOK * Cdim;
    float* vout = kout + (size_t)BHN * TFULL * HD;

    float* qkv_ptr = nullptr;
    float* y_ptr   = nullptr;
    float* pp_ptr  = nullptr;
    cudaGetSymbolAddress((void**)&qkv_ptr, g_qkv);
    cudaGetSymbolAddress((void**)&y_ptr, g_y);
    cudaGetSymbolAddress((void**)&pp_ptr, g_part);

    static int init_done = 0;
    if (!init_done) {
        cudaFuncSetAttribute(attn_split,
            cudaFuncAttributeMaxDynamicSharedMemorySize, ATTN_SMEM);
        init_done = 1;
    }

    // 1) QKV projection via tf32 split-MMA (split-K, KC=128)
    gemm_mma_splitk<<<dim3(48, KSQ), 256>>>(x, W_attn, pp_ptr, 3072, 1024, 128);
    reduce_qkv<<<384, 256>>>(pp_ptr, b_attn, qkv_ptr, kout, vout);

    // 2) fused cache copy + pipelined split attention (one wave) + combine
    attn_split<<<dim3(BHN, ASPLIT), 256, ATTN_SMEM>>>(past_k, past_v, kout, vout);
    attn_combine<<<BHN, 512>>>();

    // 3) output projection via tf32 split-MMA (split-K, KC=64)
    gemm_mma_splitk<<<dim3(16, KSP), 256>>>(y_ptr, W_proj, pp_ptr, 1024, 1024, 64);
    reduce_proj<<<128, 256>>>(pp_ptr, b_proj, out);
}

// round 14
// speedup vs baseline: 1.0586x; 1.0586x over previous
#include <cuda_runtime.h>
#include <cstdint>

#define Bn 16
#define TNEW 8
#define Cdim 1024
#define Hn 16
#define HD 64
#define TPAST 4096
#define TFULL 4104
#define BHN 256     // Bn*Hn
#define NTOK 128    // Bn*TNEW
#define KSP 16      // proj GEMM K-split (KC = 64)
#define ASPLIT 4    // attention key-split (best-measured shape)
#define NCH 16      // 64-key chunks per attention block

// scratch (no cudaMalloc allowed)
__device__ __align__(16) float g_qkv[NTOK * 3 * Cdim];        // 1.5 MB (q region used)
__device__ __align__(16) float g_y[NTOK * Cdim];              // 512 KB
__device__ __align__(16) float g_part[KSP * 128 * 1024];      // 8.4 MB (proj partials)
__device__ float g_pm[BHN * ASPLIT * 8];
__device__ float g_pl[BHN * ASPLIT * 8];
__device__ __align__(16) float g_po[BHN * ASPLIT * 8 * 64];   // 2 MB

__device__ __forceinline__ uint32_t smem_u32(const void* p) {
    return (uint32_t)__cvta_generic_to_shared(p);
}
__device__ __forceinline__ void cp16(uint32_t dst, const void* src) {
    asm volatile("cp.async.cg.shared.global [%0], [%1], 16;\n" :: "r"(dst), "l"(src));
}
__device__ __forceinline__ void cp_commit() {
    asm volatile("cp.async.commit_group;\n");
}
template <int N>
__device__ __forceinline__ void cp_wait() {
    asm volatile("cp.async.wait_group %0;\n" :: "n"(N));
}

// ---------------------------------------------------------------------------
// tf32 helpers (Markidis 2-term split -> fp32-class accuracy)
// ---------------------------------------------------------------------------
__device__ __forceinline__ void tf32_split(float a, uint32_t& hi, uint32_t& lo) {
    uint32_t h;
    asm("cvt.rna.tf32.f32 %0, %1;" : "=r"(h) : "f"(a));
    float r = a - __uint_as_float(h);
    uint32_t l;
    asm("cvt.rna.tf32.f32 %0, %1;" : "=r"(l) : "f"(r));
    hi = h; lo = l;
}

__device__ __forceinline__ void mma_tf32(float* d, const uint32_t* a, const uint32_t* b) {
    asm volatile(
        "mma.sync.aligned.m16n8k8.row.col.f32.tf32.tf32.f32 "
        "{%0,%1,%2,%3}, {%4,%5,%6,%7}, {%8,%9}, {%0,%1,%2,%3};\n"
        : "+f"(d[0]), "+f"(d[1]), "+f"(d[2]), "+f"(d[3])
        : "r"(a[0]), "r"(a[1]), "r"(a[2]), "r"(a[3]), "r"(b[0]), "r"(b[1]));
}

// ---------------------------------------------------------------------------
// Direct full-K QKV GEMM: qkv[m][n] = x[m][:] . W_attn[n][:] + b_attn[n].
// Tile 128m x 32n -> 96 blocks.  cp.async double-buffered 32-k staging.
// Epilogue: bias; q cols -> g_qkv; k/v cols -> cache tails.  NO reduce pass.
// ---------------------------------------------------------------------------
__global__ void __launch_bounds__(256) gemm_qkv_direct(
    const float* __restrict__ x, const float* __restrict__ W_attn,
    const float* __restrict__ b_attn, float* __restrict__ kout,
    float* __restrict__ vout)
{
    __shared__ float As[2][128][36];   // 36.9 KB
    __shared__ float Ws[2][32][36];    //  9.2 KB

    int n0 = blockIdx.x * 32;
    int t = threadIdx.x, lane = t & 31, wid = t >> 5;
    int grp = lane >> 2, tig = lane & 3;
    int wm = (wid >> 1) * 32;          // 4 warps over 128m
    int wn = (wid & 1) * 16;           // 2 warps over 32n

    uint32_t a_s = smem_u32(&As[0][0][0]);
    uint32_t w_s = smem_u32(&Ws[0][0][0]);
    const uint32_t a_plane = 128 * 36 * 4;
    const uint32_t w_plane = 32 * 36 * 4;

    float d[2][2][4];
    #pragma unroll
    for (int i = 0; i < 2; i++)
        #pragma unroll
        for (int j = 0; j < 2; j++)
            #pragma unroll
            for (int r = 0; r < 4; r++) d[i][j][r] = 0.f;

    // stage helper indices
    const int a_row = t >> 1;                 // with it*... see below
    // A: 1024 cp16 / 256 thr = 4 each ; W: 256 cp16 / 256 thr = 1 each

    // prefetch chunk 0
    {
        #pragma unroll
        for (int it = 0; it < 4; it++) {
            int idx = t + it * 256;
            int row = idx >> 3, c4 = (idx & 7) * 4;
            cp16(a_s + ((uint32_t)row * 36 + c4) * 4, &x[(size_t)row * 1024 + c4]);
        }
        {
            int row = t >> 3, c4 = (t & 7) * 4;
            cp16(w_s + ((uint32_t)row * 36 + c4) * 4, &W_attn[(size_t)(n0 + row) * 1024 + c4]);
        }
        cp_commit();
    }

    for (int c = 0; c < 32; c++) {
        int buf = c & 1;
        cp_wait<0>();
        __syncthreads();               // chunk c visible; compute(c-1) done

        if (c + 1 < 32) {              // prefetch chunk c+1 into other buffer
            uint32_t ab = a_s + (uint32_t)(buf ^ 1) * a_plane;
            uint32_t wb = w_s + (uint32_t)(buf ^ 1) * w_plane;
            int kofs = (c + 1) * 32;
            #pragma unroll
            for (int it = 0; it < 4; it++) {
                int idx = t + it * 256;
                int row = idx >> 3, c4 = (idx & 7) * 4;
                cp16(ab + ((uint32_t)row * 36 + c4) * 4,
                     &x[(size_t)row * 1024 + kofs + c4]);
            }
            {
                int row = t >> 3, c4 = (t & 7) * 4;
                cp16(wb + ((uint32_t)row * 36 + c4) * 4,
                     &W_attn[(size_t)(n0 + row) * 1024 + kofs + c4]);
            }
            cp_commit();
        }

        #pragma unroll
        for (int ks = 0; ks < 4; ks++) {
            int kb = ks * 8;
            uint32_t ah[2][4], al[2][4];
            #pragma unroll
            for (int i = 0; i < 2; i++) {
                int mb = wm + i * 16;
                tf32_split(As[buf][mb + grp][kb + tig],         ah[i][0], al[i][0]);
                tf32_split(As[buf][mb + grp + 8][kb + tig],     ah[i][1], al[i][1]);
                tf32_split(As[buf][mb + grp][kb + tig + 4],     ah[i][2], al[i][2]);
                tf32_split(As[buf][mb + grp + 8][kb + tig + 4], ah[i][3], al[i][3]);
            }
            uint32_t bh[2][2], bl[2][2];
            #pragma unroll
            for (int j = 0; j < 2; j++) {
                int nb = wn + j * 8;
                tf32_split(Ws[buf][nb + grp][kb + tig],     bh[j][0], bl[j][0]);
                tf32_split(Ws[buf][nb + grp][kb + tig + 4], bh[j][1], bl[j][1]);
            }
            #pragma unroll
            for (int i = 0; i < 2; i++)
                #pragma unroll
                for (int j = 0; j < 2; j++) {
                    mma_tf32(d[i][j], ah[i], bh[j]);
                    mma_tf32(d[i][j], ah[i], bl[j]);
                    mma_tf32(d[i][j], al[i], bh[j]);
                }
        }
        // no trailing sync: next iteration's top sync orders reads vs restage
    }

    // epilogue: bias + route to g_qkv (q cols) or cache tails (k/v cols)
    #pragma unroll
    for (int i = 0; i < 2; i++) {
        #pragma unroll
        for (int j = 0; j < 2; j++) {
            int m = wm + i * 16 + grp;
            int n = n0 + wn + j * 8 + tig * 2;
            float2 bias = *(const float2*)&b_attn[n];
            float2 v0 = make_float2(d[i][j][0] + bias.x, d[i][j][1] + bias.y);
            float2 v1 = make_float2(d[i][j][2] + bias.x, d[i][j][3] + bias.y);
            if (n < 1024) {
                *(float2*)&g_qkv[(size_t)m * 3072 + n]       = v0;
                *(float2*)&g_qkv[(size_t)(m + 8) * 3072 + n] = v1;
            } else {
                int isv = n >= 2048;
                int cc = n - (isv ? 2048 : 1024);
                int hh = cc >> 6, dd = cc & 63;
                float* dst = isv ? vout : kout;
                {
                    int bb = m >> 3, jj = m & 7;
                    *(float2*)&dst[(((size_t)(bb * 16 + hh)) * TFULL + TPAST + jj) * 64 + dd] = v0;
                }
                {
                    int m2 = m + 8;
                    int bb = m2 >> 3, jj = m2 & 7;
                    *(float2*)&dst[(((size_t)(bb * 16 + hh)) * TFULL + TPAST + jj) * 64 + dd] = v1;
                }
            }
        }
    }
}

// ---------------------------------------------------------------------------
// Split-K MMA GEMM for the output projection (R11-exact).
// ---------------------------------------------------------------------------
__global__ void __launch_bounds__(256) gemm_mma_splitk(
    const float* __restrict__ A, const float* __restrict__ Bw,
    float* __restrict__ part, int N, int K, int KC)
{
    __shared__ float As[128][36];
    __shared__ float Ws[64][36];

    int n0 = blockIdx.x * 64;
    int kbase = blockIdx.y * KC;
    int t = threadIdx.x, lane = t & 31, wid = t >> 5;
    int grp = lane >> 2, tig = lane & 3;
    int wm = (wid >> 1) * 32;
    int wn = (wid & 1) * 32;

    float d[2][4][4];
    #pragma unroll
    for (int i = 0; i < 2; i++)
        #pragma unroll
        for (int j = 0; j < 4; j++)
            #pragma unroll
            for (int r = 0; r < 4; r++) d[i][j][r] = 0.f;

    for (int kk = 0; kk < KC; kk += 32) {
        #pragma unroll
        for (int it = 0; it < 4; it++) {
            int idx = t + it * 256;
            int row = idx >> 3, c4 = (idx & 7) * 4;
            float4 v = *(const float4*)&A[(size_t)row * K + kbase + kk + c4];
            As[row][c4] = v.x; As[row][c4 + 1] = v.y;
            As[row][c4 + 2] = v.z; As[row][c4 + 3] = v.w;
        }
        #pragma unroll
        for (int it = 0; it < 2; it++) {
            int idx = t + it * 256;
            int row = idx >> 3, c4 = (idx & 7) * 4;
            float4 v = *(const float4*)&Bw[(size_t)(n0 + row) * K + kbase + kk + c4];
            Ws[row][c4] = v.x; Ws[row][c4 + 1] = v.y;
            Ws[row][c4 + 2] = v.z; Ws[row][c4 + 3] = v.w;
        }
        __syncthreads();

        #pragma unroll
        for (int ks = 0; ks < 4; ks++) {
            int kb = ks * 8;
            uint32_t ah[2][4], al[2][4];
            #pragma unroll
            for (int i = 0; i < 2; i++) {
                int mb = wm + i * 16;
                tf32_split(As[mb + grp][kb + tig],         ah[i][0], al[i][0]);
                tf32_split(As[mb + grp + 8][kb + tig],     ah[i][1], al[i][1]);
                tf32_split(As[mb + grp][kb + tig + 4],     ah[i][2], al[i][2]);
                tf32_split(As[mb + grp + 8][kb + tig + 4], ah[i][3], al[i][3]);
            }
            uint32_t bh[4][2], bl[4][2];
            #pragma unroll
            for (int j = 0; j < 4; j++) {
                int nb = wn + j * 8;
                tf32_split(Ws[nb + grp][kb + tig],     bh[j][0], bl[j][0]);
                tf32_split(Ws[nb + grp][kb + tig + 4], bh[j][1], bl[j][1]);
            }
            #pragma unroll
            for (int i = 0; i < 2; i++)
                #pragma unroll
                for (int j = 0; j < 4; j++) {
                    mma_tf32(d[i][j], ah[i], bh[j]);
                    mma_tf32(d[i][j], ah[i], bl[j]);
                    mma_tf32(d[i][j], al[i], bh[j]);
                }
        }
        __syncthreads();
    }

    float* pout = part + (size_t)blockIdx.y * 128 * N;
    #pragma unroll
    for (int i = 0; i < 2; i++) {
        #pragma unroll
        for (int j = 0; j < 4; j++) {
            int m = wm + i * 16 + grp;
            int n = n0 + wn + j * 8 + tig * 2;
            *(float2*)&pout[(size_t)m * N + n]       = make_float2(d[i][j][0], d[i][j][1]);
            *(float2*)&pout[(size_t)(m + 8) * N + n] = make_float2(d[i][j][2], d[i][j][3]);
        }
    }
}

// reduce projection partials + bias -> out
__global__ void __launch_bounds__(256) reduce_proj(
    const float* __restrict__ part, const float* __restrict__ bias,
    float* __restrict__ out)
{
    int idx = blockIdx.x * 256 + threadIdx.x;   // 128 * 256
    int m = idx >> 8, n = idx & 255;
    float4 s = *(const float4*)&bias[n * 4];
    #pragma unroll
    for (int ks = 0; ks < KSP; ks++) {
        float4 p = *(const float4*)&part[((size_t)ks * 128 + m) * 1024 + n * 4];
        s.x += p.x; s.y += p.y; s.z += p.z; s.w += p.w;
    }
    *(float4*)&out[(size_t)m * 1024 + n * 4] = s;
}

// ---------------------------------------------------------------------------
// Pipelined split attention (R6/R11-exact).  grid (BHN, ASPLIT=4).
// ---------------------------------------------------------------------------
__device__ __forceinline__ void softmax_update10(
    float* Ss, float* m_s, float* l_s, float* f_s, int lane, int wid)
{
    int j = wid;
    float v0 = Ss[lane * 10 + j];
    float v1 = Ss[(lane + 32) * 10 + j];
    float mx = fmaxf(v0, v1);
    #pragma unroll
    for (int o = 16; o; o >>= 1) mx = fmaxf(mx, __shfl_xor_sync(0xffffffffu, mx, o));
    float m_old = m_s[j];
    float m_new = fmaxf(m_old, mx);
    float p0 = __expf(v0 - m_new);
    float p1 = __expf(v1 - m_new);
    Ss[lane * 10 + j] = p0;
    Ss[(lane + 32) * 10 + j] = p1;
    float sum = p0 + p1;
    #pragma unroll
    for (int o = 16; o; o >>= 1) sum += __shfl_xor_sync(0xffffffffu, sum, o);
    if (lane == 0) {
        float f = __expf(m_old - m_new);
        l_s[j] = l_s[j] * f + sum;
        m_s[j] = m_new;
        f_s[j] = f;
    }
}

// dynamic smem layout (bytes):
//   qs: 0..2048 | k_sm: 2048..34816 (2x) | v_sm: 34816..51200 (1x)
//   Ss: 51200..53760 | m/l/f: 53760..53856 | red: 53856..55904
#define ATTN_SMEM 55904

__global__ void __launch_bounds__(256, 4) attn_split(
    const float* __restrict__ past_k, const float* __restrict__ past_v,
    float* __restrict__ kout, float* __restrict__ vout)
{
    extern __shared__ char smraw[];
    float*  qs   = (float*)smraw;
    float4* k_sm = (float4*)(smraw + 2048);
    float4* v_sm = (float4*)(smraw + 34816);
    float*  Ss   = (float*)(smraw + 51200);
    float*  m_s  = (float*)(smraw + 53760);
    float*  l_s  = m_s + 8;
    float*  f_s  = m_s + 16;
    float4* red  = (float4*)(smraw + 53856);

    int bh = blockIdx.x;
    int s  = blockIdx.y;
    int b = bh >> 4, h = bh & 15;
    int t = threadIdx.x, lane = t & 31, wid = t >> 5;

    // load q (scale folded: 1/sqrt(64) = 0.125)
    for (int i = t; i < 512; i += 256) {
        int j = i >> 6, d = i & 63;
        qs[i] = g_qkv[(size_t)(b * 8 + j) * 3072 + h * 64 + d] * 0.125f;
    }
    if (t < 8) { m_s[t] = -3.0e38f; l_s[t] = 0.f; }

    const float4* ksrc = (const float4*)past_k + (size_t)bh * TPAST * 16;
    const float4* vsrc = (const float4*)past_v + (size_t)bh * TPAST * 16;
    float4* kdst = (float4*)kout + (size_t)bh * TFULL * 16;
    float4* vdst = (float4*)vout + (size_t)bh * TFULL * 16;
    const float4* q4 = (const float4*)qs;
    const float2* v2s = (const float2*)v_sm;

    const int ld_r = t >> 4, ld_d4 = t & 15;
    uint32_t k_b0 = smem_u32(k_sm), v_b0 = smem_u32(v_sm);

    const int j2 = (wid & 3) * 2;
    const int r_sc = (wid >> 2) * 32 + lane;
    const int jp = t >> 6;
    const int rh = (t >> 5) & 1;
    const int d2 = lane;

    float accA0 = 0.f, accA1 = 0.f, accB0 = 0.f, accB1 = 0.f;

    const int c_begin = s * (TPAST / ASPLIT);

    // prefetch k chunk 0
    #pragma unroll
    for (int it = 0; it < 4; it++) {
        int r = ld_r + it * 16;
        int sw = r * 16 + (ld_d4 ^ (r & 15));
        cp16(k_b0 + (uint32_t)sw * 16, ksrc + (size_t)(c_begin + r) * 16 + ld_d4);
    }
    cp_commit();

    for (int ci = 0; ci < NCH; ci++) {
        int c0 = c_begin + ci * 64;
        int buf = ci & 1;
        cp_wait<0>();
        __syncthreads();       // sync_a: k(ci) visible; accum(ci-1) done

        #pragma unroll
        for (int it = 0; it < 4; it++) {
            int r = ld_r + it * 16;
            int sw = r * 16 + (ld_d4 ^ (r & 15));
            cp16(v_b0 + (uint32_t)sw * 16, vsrc + (size_t)(c0 + r) * 16 + ld_d4);
        }
        cp_commit();

        bool more = (ci + 1 < NCH);
        if (more) {
            uint32_t kb = k_b0 + (uint32_t)(buf ^ 1) * 16384;
            #pragma unroll
            for (int it = 0; it < 4; it++) {
                int r = ld_r + it * 16;
                int sw = r * 16 + (ld_d4 ^ (r & 15));
                cp16(kb + (uint32_t)sw * 16, ksrc + (size_t)(c0 + 64 + r) * 16 + ld_d4);
            }
            cp_commit();
        }

        const float4* kbp = k_sm + buf * 1024;

        #pragma unroll
        for (int it = 0; it < 4; it++) {
            int r = ld_r + it * 16;
            int sw = r * 16 + (ld_d4 ^ (r & 15));
            __stcs(&kdst[(size_t)(c0 + r) * 16 + ld_d4], kbp[sw]);
        }

        {
            int r = r_sc;
            float s0 = 0.f, s1 = 0.f;
            #pragma unroll
            for (int d4 = 0; d4 < 16; d4++) {
                float4 kv = kbp[r * 16 + (d4 ^ (r & 15))];
                float4 qa = q4[j2 * 16 + d4];
                float4 qb = q4[(j2 + 1) * 16 + d4];
                s0 += kv.x * qa.x + kv.y * qa.y + kv.z * qa.z + kv.w * qa.w;
                s1 += kv.x * qb.x + kv.y * qb.y + kv.z * qb.z + kv.w * qb.w;
            }
            Ss[r * 10 + j2]     = s0;
            Ss[r * 10 + j2 + 1] = s1;
        }
        __syncthreads();       // sync_b
        softmax_update10(Ss, m_s, l_s, f_s, lane, wid);
        if (more) cp_wait<1>(); else cp_wait<0>();
        __syncthreads();       // sync_c

        {
            float f0 = f_s[2 * jp], f1 = f_s[2 * jp + 1];
            accA0 *= f0; accA1 *= f0; accB0 *= f1; accB1 *= f1;
        }
        #pragma unroll
        for (int it = 0; it < 4; it++) {
            int r = ld_r + it * 16;
            int sw = r * 16 + (ld_d4 ^ (r & 15));
            __stcs(&vdst[(size_t)(c0 + r) * 16 + ld_d4], v_sm[sw]);
        }
        {
            int d4 = d2 >> 1, dlo = d2 & 1;
            #pragma unroll 8
            for (int rr = 0; rr < 32; rr++) {
                int r = rh * 32 + rr;
                float2 p = *(const float2*)&Ss[r * 10 + 2 * jp];
                float2 vv = v2s[(r * 16 + (d4 ^ (r & 15))) * 2 + dlo];
                accA0 += p.x * vv.x; accA1 += p.x * vv.y;
                accB0 += p.y * vv.x; accB1 += p.y * vv.y;
            }
        }
    }
    __syncthreads();

    // =================== last split: 8 new keys (causal mask) ==============
    if (s == ASPLIT - 1) {
        if (t < 128) {
            int r = t >> 4, d4 = t & 15;
            k_sm[r * 16 + (d4 ^ (r & 15))] = kdst[(size_t)(TPAST + r) * 16 + d4];
        } else {
            int tt = t - 128;
            int r = tt >> 4, d4 = tt & 15;
            v_sm[r * 16 + (d4 ^ (r & 15))] = vdst[(size_t)(TPAST + r) * 16 + d4];
        }
        __syncthreads();
        {
            int r = r_sc;
            float s0 = -3.0e38f, s1 = -3.0e38f;
            if (r < 8) {
                float a0 = 0.f, a1 = 0.f;
                #pragma unroll
                for (int d4 = 0; d4 < 16; d4++) {
                    float4 kv = k_sm[r * 16 + (d4 ^ (r & 15))];
                    float4 qa = q4[j2 * 16 + d4];
                    float4 qb = q4[(j2 + 1) * 16 + d4];
                    a0 += kv.x * qa.x + kv.y * qa.y + kv.z * qa.z + kv.w * qa.w;
                    a1 += kv.x * qb.x + kv.y * qb.y + kv.z * qb.z + kv.w * qb.w;
                }
                if (r <= j2)     s0 = a0;
                if (r <= j2 + 1) s1 = a1;
            }
            Ss[r * 10 + j2]     = s0;
            Ss[r * 10 + j2 + 1] = s1;
        }
        __syncthreads();
        softmax_update10(Ss, m_s, l_s, f_s, lane, wid);
        __syncthreads();
        {
            float f0 = f_s[2 * jp], f1 = f_s[2 * jp + 1];
            accA0 *= f0; accA1 *= f0; accB0 *= f1; accB1 *= f1;
        }
        if (rh == 0) {
            int d4 = d2 >> 1, dlo = d2 & 1;
            #pragma unroll
            for (int r = 0; r < 8; r++) {
                float2 p = *(const float2*)&Ss[r * 10 + 2 * jp];
                float2 vv = v2s[(r * 16 + (d4 ^ (r & 15))) * 2 + dlo];
                accA0 += p.x * vv.x; accA1 += p.x * vv.y;
                accB0 += p.y * vv.x; accB1 += p.y * vv.y;
            }
        }
        __syncthreads();
    }

    // cross-half reduce + store partials
    if (rh == 1) red[jp * 32 + d2] = make_float4(accA0, accA1, accB0, accB1);
    __syncthreads();
    if (rh == 0) {
        float4 o = red[jp * 32 + d2];
        accA0 += o.x; accA1 += o.y; accB0 += o.z; accB1 += o.w;
        int j0 = 2 * jp, j1 = 2 * jp + 1;
        size_t base = (size_t)(bh * ASPLIT + s) * 8;
        g_po[(base + j0) * 64 + 2 * d2]     = accA0;
        g_po[(base + j0) * 64 + 2 * d2 + 1] = accA1;
        g_po[(base + j1) * 64 + 2 * d2]     = accB0;
        g_po[(base + j1) * 64 + 2 * d2 + 1] = accB1;
    }
    if (t < 8) {
        g_pm[(bh * ASPLIT + s) * 8 + t] = m_s[t];
        g_pl[(bh * ASPLIT + s) * 8 + t] = l_s[t];
    }
}

// combine split partials -> g_y (token-major for projection GEMM)
__global__ void __launch_bounds__(512) attn_combine()
{
    int bh = blockIdx.x;
    int b = bh >> 4, h = bh & 15;
    int t = threadIdx.x;
    int j = t >> 6, d = t & 63;

    float mm[ASPLIT], ll[ASPLIT];
    float m_g = -3.0e38f;
    #pragma unroll
    for (int s = 0; s < ASPLIT; s++) {
        mm[s] = g_pm[(bh * ASPLIT + s) * 8 + j];
        ll[s] = g_pl[(bh * ASPLIT + s) * 8 + j];
        m_g = fmaxf(m_g, mm[s]);
    }
    float l_g = 0.f, o = 0.f;
    #pragma unroll
    for (int s = 0; s < ASPLIT; s++) {
        float w = __expf(mm[s] - m_g);
        l_g += ll[s] * w;
        o += g_po[((size_t)(bh * ASPLIT + s) * 8 + j) * 64 + d] * w;
    }
    g_y[(size_t)(b * 8 + j) * Cdim + h * 64 + d] = o / l_g;
}

// ---------------------------------------------------------------------------
// kernel_launch (single stream):
//   gemm_qkv_direct(+bias+scatter) -> attn_split -> attn_combine
//   -> gemm_mma_splitk(proj) -> reduce_proj
// ---------------------------------------------------------------------------
extern "C" void kernel_launch(void* const* d_in, const int* in_sizes, int n_in,
                              void* d_out, int out_size)
{
    const float* x      = (const float*)d_in[0];
    const float* past_k = (const float*)d_in[1];
    const float* past_v = (const float*)d_in[2];
    const float* W_attn = (const float*)d_in[3];
    const float* b_attn = (const float*)d_in[4];
    const float* W_proj = (const float*)d_in[5];
    const float* b_proj = (const float*)d_in[6];

    float* out  = (float*)d_out;
    float* kout = out + (size_t)NTOK * Cdim;
    float* vout = kout + (size_t)BHN * TFULL * HD;

    float* y_ptr  = nullptr;
    float* pp_ptr = nullptr;
    cudaGetSymbolAddress((void**)&y_ptr, g_y);
    cudaGetSymbolAddress((void**)&pp_ptr, g_part);

    static int init_done = 0;
    if (!init_done) {
        cudaFuncSetAttribute(attn_split,
            cudaFuncAttributeMaxDynamicSharedMemorySize, ATTN_SMEM);
        init_done = 1;
    }

    // 1) QKV projection: direct full-K MMA GEMM with fused bias + scatter
    gemm_qkv_direct<<<96, 256>>>(x, W_attn, b_attn, kout, vout);

    // 2) fused cache copy + pipelined split attention + combine
    attn_split<<<dim3(BHN, ASPLIT), 256, ATTN_SMEM>>>(past_k, past_v, kout, vout);
    attn_combine<<<BHN, 512>>>();

    // 3) output projection via tf32 split-MMA (split-K, KC=64)
    gemm_mma_splitk<<<dim3(16, KSP), 256>>>(y_ptr, W_proj, pp_ptr, 1024, 1024, 64);
    reduce_proj<<<128, 256>>>(pp_ptr, b_proj, out);
}

// round 16
// speedup vs baseline: 1.1202x; 1.0582x over previous
#include <cuda_runtime.h>
#include <cstdint>

#define Bn 16
#define TNEW 8
#define Cdim 1024
#define Hn 16
#define HD 64
#define TPAST 4096
#define TFULL 4104
#define BHN 256     // Bn*Hn
#define NTOK 128    // Bn*TNEW
#define KSQ 8       // QKV GEMM K-split (KC = 128)
#define KSP 16      // proj GEMM K-split (KC = 64)
#define ASPLIT 4    // attention key-split
#define NCH 16      // 64-key chunks per attention block

// scratch (no cudaMalloc allowed)
__device__ __align__(16) float g_q[NTOK * Cdim];              // 512 KB (q only)
__device__ __align__(16) float g_y[NTOK * Cdim];              // 512 KB
__device__ __align__(16) float g_part[KSQ * 128 * 3072];      // 12.6 MB
__device__ float g_pm[BHN * ASPLIT * 8];
__device__ float g_pl[BHN * ASPLIT * 8];
__device__ __align__(16) float g_po[BHN * ASPLIT * 8 * 64];   // 2 MB

__device__ __forceinline__ uint32_t smem_u32(const void* p) {
    return (uint32_t)__cvta_generic_to_shared(p);
}
__device__ __forceinline__ void cp16(uint32_t dst, const void* src) {
    asm volatile("cp.async.cg.shared.global [%0], [%1], 16;\n" :: "r"(dst), "l"(src));
}
__device__ __forceinline__ void cp_commit() {
    asm volatile("cp.async.commit_group;\n");
}
template <int N>
__device__ __forceinline__ void cp_wait() {
    asm volatile("cp.async.wait_group %0;\n" :: "n"(N));
}

// ---------------------------------------------------------------------------
// tf32 split-MMA GEMM (Markidis 2-term split), register double-buffered
// global loads.  part[ks][m][n] = sum_{k in chunk} A[m][k]*Bw[n][k].
// Block tile: 128m x 64n, 256 threads (8 warps as 4m x 2n), 32-k chunks.
// ---------------------------------------------------------------------------
__device__ __forceinline__ void tf32_split(float a, uint32_t& hi, uint32_t& lo) {
    uint32_t h;
    asm("cvt.rna.tf32.f32 %0, %1;" : "=r"(h) : "f"(a));
    float r = a - __uint_as_float(h);
    uint32_t l;
    asm("cvt.rna.tf32.f32 %0, %1;" : "=r"(l) : "f"(r));
    hi = h; lo = l;
}

__device__ __forceinline__ void mma_tf32(float* d, const uint32_t* a, const uint32_t* b) {
    asm volatile(
        "mma.sync.aligned.m16n8k8.row.col.f32.tf32.tf32.f32 "
        "{%0,%1,%2,%3}, {%4,%5,%6,%7}, {%8,%9}, {%0,%1,%2,%3};\n"
        : "+f"(d[0]), "+f"(d[1]), "+f"(d[2]), "+f"(d[3])
        : "r"(a[0]), "r"(a[1]), "r"(a[2]), "r"(a[3]), "r"(b[0]), "r"(b[1]));
}

__global__ void __launch_bounds__(256) gemm_mma_splitk(
    const float* __restrict__ A, const float* __restrict__ Bw,
    float* __restrict__ part, int N, int K, int KC)
{
    __shared__ float As[128][36];   // pad 36: conflict-free fragment gathers
    __shared__ float Ws[64][36];

    int n0 = blockIdx.x * 64;
    int kbase = blockIdx.y * KC;
    int t = threadIdx.x, lane = t & 31, wid = t >> 5;
    int grp = lane >> 2, tig = lane & 3;
    int wm = (wid >> 1) * 32;       // warp m offset (4 warps over 128m)
    int wn = (wid & 1) * 32;        // warp n offset (2 warps over 64n)

    // staging indices (fixed per thread)
    // A: 1024 float4s / 256 thr = 4 each ; W: 512 float4s / 256 thr = 2 each
    int ar[4], ac[4];
    #pragma unroll
    for (int it = 0; it < 4; it++) {
        int idx = t + it * 256;
        ar[it] = idx >> 3; ac[it] = (idx & 7) * 4;
    }
    int wr[2], wc[2];
    #pragma unroll
    for (int it = 0; it < 2; it++) {
        int idx = t + it * 256;
        wr[it] = idx >> 3; wc[it] = (idx & 7) * 4;
    }

    float d[2][4][4];
    #pragma unroll
    for (int i = 0; i < 2; i++)
        #pragma unroll
        for (int j = 0; j < 4; j++)
            #pragma unroll
            for (int r = 0; r < 4; r++) d[i][j][r] = 0.f;

    // preload chunk 0 into registers
    float4 ra[4], rw[2];
    #pragma unroll
    for (int it = 0; it < 4; it++)
        ra[it] = *(const float4*)&A[(size_t)ar[it] * K + kbase + ac[it]];
    #pragma unroll
    for (int it = 0; it < 2; it++)
        rw[it] = *(const float4*)&Bw[(size_t)(n0 + wr[it]) * K + kbase + wc[it]];

    for (int kk = 0; kk < KC; kk += 32) {
        // store staged chunk
        #pragma unroll
        for (int it = 0; it < 4; it++) {
            As[ar[it]][ac[it]]     = ra[it].x; As[ar[it]][ac[it] + 1] = ra[it].y;
            As[ar[it]][ac[it] + 2] = ra[it].z; As[ar[it]][ac[it] + 3] = ra[it].w;
        }
        #pragma unroll
        for (int it = 0; it < 2; it++) {
            Ws[wr[it]][wc[it]]     = rw[it].x; Ws[wr[it]][wc[it] + 1] = rw[it].y;
            Ws[wr[it]][wc[it] + 2] = rw[it].z; Ws[wr[it]][wc[it] + 3] = rw[it].w;
        }
        __syncthreads();

        if (kk + 32 < KC) {   // prefetch next chunk (latency hidden by compute)
            #pragma unroll
            for (int it = 0; it < 4; it++)
                ra[it] = *(const float4*)&A[(size_t)ar[it] * K + kbase + kk + 32 + ac[it]];
            #pragma unroll
            for (int it = 0; it < 2; it++)
                rw[it] = *(const float4*)&Bw[(size_t)(n0 + wr[it]) * K + kbase + kk + 32 + wc[it]];
        }

        #pragma unroll
        for (int ks = 0; ks < 4; ks++) {
            int kb = ks * 8;
            uint32_t ah[2][4], al[2][4];
            #pragma unroll
            for (int i = 0; i < 2; i++) {
                int mb = wm + i * 16;
                tf32_split(As[mb + grp][kb + tig],         ah[i][0], al[i][0]);
                tf32_split(As[mb + grp + 8][kb + tig],     ah[i][1], al[i][1]);
                tf32_split(As[mb + grp][kb + tig + 4],     ah[i][2], al[i][2]);
                tf32_split(As[mb + grp + 8][kb + tig + 4], ah[i][3], al[i][3]);
            }
            uint32_t bh[4][2], bl[4][2];
            #pragma unroll
            for (int j = 0; j < 4; j++) {
                int nb = wn + j * 8;
                tf32_split(Ws[nb + grp][kb + tig],     bh[j][0], bl[j][0]);
                tf32_split(Ws[nb + grp][kb + tig + 4], bh[j][1], bl[j][1]);
            }
            #pragma unroll
            for (int i = 0; i < 2; i++)
                #pragma unroll
                for (int j = 0; j < 4; j++) {
                    mma_tf32(d[i][j], ah[i], bh[j]);   // hi*hi
                    mma_tf32(d[i][j], ah[i], bl[j]);   // hi*lo
                    mma_tf32(d[i][j], al[i], bh[j]);   // lo*hi
                }
        }
        __syncthreads();
    }

    // epilogue: write partials (fragment layout -> (m, n) coords)
    float* pout = part + (size_t)blockIdx.y * 128 * N;
    #pragma unroll
    for (int i = 0; i < 2; i++) {
        #pragma unroll
        for (int j = 0; j < 4; j++) {
            int m = wm + i * 16 + grp;
            int n = n0 + wn + j * 8 + tig * 2;
            *(float2*)&pout[(size_t)m * N + n]       = make_float2(d[i][j][0], d[i][j][1]);
            *(float2*)&pout[(size_t)(m + 8) * N + n] = make_float2(d[i][j][2], d[i][j][3]);
        }
    }
}

// reduce QKV partials + bias: q cols -> g_q (dense), k/v cols -> cache tails
__global__ void __launch_bounds__(256) reduce_qkv(
    const float* __restrict__ part, const float* __restrict__ bias,
    float* __restrict__ kout, float* __restrict__ vout)
{
    int idx = blockIdx.x * 256 + threadIdx.x;   // 128 * 768
    int m = idx / 768, n = idx % 768;
    float4 s = *(const float4*)&bias[n * 4];
    #pragma unroll
    for (int ks = 0; ks < KSQ; ks++) {
        float4 p = *(const float4*)&part[((size_t)ks * 128 + m) * 3072 + n * 4];
        s.x += p.x; s.y += p.y; s.z += p.z; s.w += p.w;
    }

    int c = n * 4;
    if (c < 1024) {
        *(float4*)&g_q[(size_t)m * 1024 + c] = s;
    } else {
        int isv = c >= 2048;
        int cc = c - (isv ? 2048 : 1024);
        int hh = cc >> 6, d = cc & 63;
        int bb = m >> 3, j = m & 7;
        float* dst = isv ? vout : kout;
        *(float4*)&dst[(((size_t)(bb * 16 + hh)) * TFULL + TPAST + j) * 64 + d] = s;
    }
}

// reduce projection partials + bias -> out
__global__ void __launch_bounds__(256) reduce_proj(
    const float* __restrict__ part, const float* __restrict__ bias,
    float* __restrict__ out)
{
    int idx = blockIdx.x * 256 + threadIdx.x;   // 128 * 256
    int m = idx >> 8, n = idx & 255;
    float4 s = *(const float4*)&bias[n * 4];
    #pragma unroll
    for (int ks = 0; ks < KSP; ks++) {
        float4 p = *(const float4*)&part[((size_t)ks * 128 + m) * 1024 + n * 4];
        s.x += p.x; s.y += p.y; s.z += p.z; s.w += p.w;
    }
    *(float4*)&out[(size_t)m * 1024 + n * 4] = s;
}

// ---------------------------------------------------------------------------
// Pipelined split attention (R6/R11-exact).  grid (BHN, ASPLIT=4).
// 64-key chunks; k double-buffered cp.async; v single-buffered deferred;
// fused cache copy.  55.9KB smem -> 4 blocks/SM.
// ---------------------------------------------------------------------------
__device__ __forceinline__ void softmax_update10(
    float* Ss, float* m_s, float* l_s, float* f_s, int lane, int wid)
{
    int j = wid;                       // warp w owns query row j=w
    float v0 = Ss[lane * 10 + j];
    float v1 = Ss[(lane + 32) * 10 + j];
    float mx = fmaxf(v0, v1);
    #pragma unroll
    for (int o = 16; o; o >>= 1) mx = fmaxf(mx, __shfl_xor_sync(0xffffffffu, mx, o));
    float m_old = m_s[j];
    float m_new = fmaxf(m_old, mx);
    float p0 = __expf(v0 - m_new);
    float p1 = __expf(v1 - m_new);
    Ss[lane * 10 + j] = p0;
    Ss[(lane + 32) * 10 + j] = p1;
    float sum = p0 + p1;
    #pragma unroll
    for (int o = 16; o; o >>= 1) sum += __shfl_xor_sync(0xffffffffu, sum, o);
    if (lane == 0) {
        float f = __expf(m_old - m_new);
        l_s[j] = l_s[j] * f + sum;
        m_s[j] = m_new;
        f_s[j] = f;
    }
}

// dynamic smem layout (bytes):
//   qs: 0..2048 | k_sm: 2048..34816 (2x) | v_sm: 34816..51200 (1x)
//   Ss: 51200..53760 | m/l/f: 53760..53856 | red: 53856..55904
#define ATTN_SMEM 55904

__global__ void __launch_bounds__(256, 4) attn_split(
    const float* __restrict__ past_k, const float* __restrict__ past_v,
    float* __restrict__ kout, float* __restrict__ vout)
{
    extern __shared__ char smraw[];
    float*  qs   = (float*)smraw;
    float4* k_sm = (float4*)(smraw + 2048);
    float4* v_sm = (float4*)(smraw + 34816);
    float*  Ss   = (float*)(smraw + 51200);
    float*  m_s  = (float*)(smraw + 53760);
    float*  l_s  = m_s + 8;
    float*  f_s  = m_s + 16;
    float4* red  = (float4*)(smraw + 53856);

    int bh = blockIdx.x;
    int s  = blockIdx.y;
    int b = bh >> 4, h = bh & 15;
    int t = threadIdx.x, lane = t & 31, wid = t >> 5;

    // load q (scale folded: 1/sqrt(64) = 0.125)
    for (int i = t; i < 512; i += 256) {
        int j = i >> 6, d = i & 63;
        qs[i] = g_q[(size_t)(b * 8 + j) * 1024 + h * 64 + d] * 0.125f;
    }
    if (t < 8) { m_s[t] = -3.0e38f; l_s[t] = 0.f; }

    const float4* ksrc = (const float4*)past_k + (size_t)bh * TPAST * 16;
    const float4* vsrc = (const float4*)past_v + (size_t)bh * TPAST * 16;
    float4* kdst = (float4*)kout + (size_t)bh * TFULL * 16;
    float4* vdst = (float4*)vout + (size_t)bh * TFULL * 16;
    const float4* q4 = (const float4*)qs;
    const float2* v2s = (const float2*)v_sm;

    const int ld_r = t >> 4, ld_d4 = t & 15;
    uint32_t k_b0 = smem_u32(k_sm), v_b0 = smem_u32(v_sm);

    const int j2 = (wid & 3) * 2;
    const int r_sc = (wid >> 2) * 32 + lane;
    const int jp = t >> 6;
    const int rh = (t >> 5) & 1;
    const int d2 = lane;

    float accA0 = 0.f, accA1 = 0.f, accB0 = 0.f, accB1 = 0.f;

    const int c_begin = s * (TPAST / ASPLIT);

    // prefetch k chunk 0
    #pragma unroll
    for (int it = 0; it < 4; it++) {
        int r = ld_r + it * 16;
        int sw = r * 16 + (ld_d4 ^ (r & 15));
        cp16(k_b0 + (uint32_t)sw * 16, ksrc + (size_t)(c_begin + r) * 16 + ld_d4);
    }
    cp_commit();

    for (int ci = 0; ci < NCH; ci++) {
        int c0 = c_begin + ci * 64;
        int buf = ci & 1;
        cp_wait<0>();          // only k(ci) outstanding here
        __syncthreads();       // sync_a: k(ci) visible; accum(ci-1) done

        // issue v(ci) into the single v buffer (now safe to overwrite)
        #pragma unroll
        for (int it = 0; it < 4; it++) {
            int r = ld_r + it * 16;
            int sw = r * 16 + (ld_d4 ^ (r & 15));
            cp16(v_b0 + (uint32_t)sw * 16, vsrc + (size_t)(c0 + r) * 16 + ld_d4);
        }
        cp_commit();

        bool more = (ci + 1 < NCH);
        if (more) {            // prefetch k(ci+1) into the other k buffer
            uint32_t kb = k_b0 + (uint32_t)(buf ^ 1) * 16384;
            #pragma unroll
            for (int it = 0; it < 4; it++) {
                int r = ld_r + it * 16;
                int sw = r * 16 + (ld_d4 ^ (r & 15));
                cp16(kb + (uint32_t)sw * 16, ksrc + (size_t)(c0 + 64 + r) * 16 + ld_d4);
            }
            cp_commit();
        }

        const float4* kbp = k_sm + buf * 1024;

        // ---- copy k chunk to cache (streaming STG from smem) ----
        #pragma unroll
        for (int it = 0; it < 4; it++) {
            int r = ld_r + it * 16;
            int sw = r * 16 + (ld_d4 ^ (r & 15));
            __stcs(&kdst[(size_t)(c0 + r) * 16 + ld_d4], kbp[sw]);
        }

        // ---- scores: warp-uniform q (broadcast LDS), per-lane key ----
        {
            int r = r_sc;
            float s0 = 0.f, s1 = 0.f;
            #pragma unroll
            for (int d4 = 0; d4 < 16; d4++) {
                float4 kv = kbp[r * 16 + (d4 ^ (r & 15))];
                float4 qa = q4[j2 * 16 + d4];
                float4 qb = q4[(j2 + 1) * 16 + d4];
                s0 += kv.x * qa.x + kv.y * qa.y + kv.z * qa.z + kv.w * qa.w;
                s1 += kv.x * qb.x + kv.y * qb.y + kv.z * qb.z + kv.w * qb.w;
            }
            Ss[r * 10 + j2]     = s0;
            Ss[r * 10 + j2 + 1] = s1;
        }
        __syncthreads();       // sync_b: scores written
        softmax_update10(Ss, m_s, l_s, f_s, lane, wid);
        if (more) cp_wait<1>(); else cp_wait<0>();   // v(ci) arrived
        __syncthreads();       // sync_c: p, f, and v visible

        {
            float f0 = f_s[2 * jp], f1 = f_s[2 * jp + 1];
            accA0 *= f0; accA1 *= f0; accB0 *= f1; accB1 *= f1;
        }
        // ---- copy v chunk to cache ----
        #pragma unroll
        for (int it = 0; it < 4; it++) {
            int r = ld_r + it * 16;
            int sw = r * 16 + (ld_d4 ^ (r & 15));
            __stcs(&vdst[(size_t)(c0 + r) * 16 + ld_d4], v_sm[sw]);
        }
        // ---- accumulate: p pair broadcast, v float2 shared by 2 queries ----
        {
            int d4 = d2 >> 1, dlo = d2 & 1;
            #pragma unroll 8
            for (int rr = 0; rr < 32; rr++) {
                int r = rh * 32 + rr;
                float2 p = *(const float2*)&Ss[r * 10 + 2 * jp];
                float2 vv = v2s[(r * 16 + (d4 ^ (r & 15))) * 2 + dlo];
                accA0 += p.x * vv.x; accA1 += p.x * vv.y;
                accB0 += p.y * vv.x; accB1 += p.y * vv.y;
            }
        }
        // no trailing sync: next iteration's sync_a orders accum vs reuse
    }
    __syncthreads();           // protect k_sm/v_sm before tail reuse

    // =================== last split: 8 new keys (causal mask) ==============
    if (s == ASPLIT - 1) {
        if (t < 128) {
            int r = t >> 4, d4 = t & 15;
            k_sm[r * 16 + (d4 ^ (r & 15))] = kdst[(size_t)(TPAST + r) * 16 + d4];
        } else {
            int tt = t - 128;
            int r = tt >> 4, d4 = tt & 15;
            v_sm[r * 16 + (d4 ^ (r & 15))] = vdst[(size_t)(TPAST + r) * 16 + d4];
        }
        __syncthreads();
        {
            int r = r_sc;
            float s0 = -3.0e38f, s1 = -3.0e38f;
            if (r < 8) {
                float a0 = 0.f, a1 = 0.f;
                #pragma unroll
                for (int d4 = 0; d4 < 16; d4++) {
                    float4 kv = k_sm[r * 16 + (d4 ^ (r & 15))];
                    float4 qa = q4[j2 * 16 + d4];
                    float4 qb = q4[(j2 + 1) * 16 + d4];
                    a0 += kv.x * qa.x + kv.y * qa.y + kv.z * qa.z + kv.w * qa.w;
                    a1 += kv.x * qb.x + kv.y * qb.y + kv.z * qb.z + kv.w * qb.w;
                }
                if (r <= j2)     s0 = a0;
                if (r <= j2 + 1) s1 = a1;
            }
            Ss[r * 10 + j2]     = s0;
            Ss[r * 10 + j2 + 1] = s1;
        }
        __syncthreads();
        softmax_update10(Ss, m_s, l_s, f_s, lane, wid);
        __syncthreads();
        {
            float f0 = f_s[2 * jp], f1 = f_s[2 * jp + 1];
            accA0 *= f0; accA1 *= f0; accB0 *= f1; accB1 *= f1;
        }
        if (rh == 0) {
            int d4 = d2 >> 1, dlo = d2 & 1;
            #pragma unroll
            for (int r = 0; r < 8; r++) {
                float2 p = *(const float2*)&Ss[r * 10 + 2 * jp];
                float2 vv = v2s[(r * 16 + (d4 ^ (r & 15))) * 2 + dlo];
                accA0 += p.x * vv.x; accA1 += p.x * vv.y;
                accB0 += p.y * vv.x; accB1 += p.y * vv.y;
            }
        }
        __syncthreads();
    }

    // cross-half reduce + store partials
    if (rh == 1) red[jp * 32 + d2] = make_float4(accA0, accA1, accB0, accB1);
    __syncthreads();
    if (rh == 0) {
        float4 o = red[jp * 32 + d2];
        accA0 += o.x; accA1 += o.y; accB0 += o.z; accB1 += o.w;
        int j0 = 2 * jp, j1 = 2 * jp + 1;
        size_t base = (size_t)(bh * ASPLIT + s) * 8;
        g_po[(base + j0) * 64 + 2 * d2]     = accA0;
        g_po[(base + j0) * 64 + 2 * d2 + 1] = accA1;
        g_po[(base + j1) * 64 + 2 * d2]     = accB0;
        g_po[(base + j1) * 64 + 2 * d2 + 1] = accB1;
    }
    if (t < 8) {
        g_pm[(bh * ASPLIT + s) * 8 + t] = m_s[t];
        g_pl[(bh * ASPLIT + s) * 8 + t] = l_s[t];
    }
}

// combine split partials -> g_y (token-major for projection GEMM)
__global__ void __launch_bounds__(512) attn_combine()
{
    int bh = blockIdx.x;
    int b = bh >> 4, h = bh & 15;
    int t = threadIdx.x;
    int j = t >> 6, d = t & 63;

    float mm[ASPLIT], ll[ASPLIT];
    float m_g = -3.0e38f;
    #pragma unroll
    for (int s = 0; s < ASPLIT; s++) {
        mm[s] = g_pm[(bh * ASPLIT + s) * 8 + j];
        ll[s] = g_pl[(bh * ASPLIT + s) * 8 + j];
        m_g = fmaxf(m_g, mm[s]);
    }
    float l_g = 0.f, o = 0.f;
    #pragma unroll
    for (int s = 0; s < ASPLIT; s++) {
        float w = __expf(mm[s] - m_g);
        l_g += ll[s] * w;
        o += g_po[((size_t)(bh * ASPLIT + s) * 8 + j) * 64 + d] * w;
    }
    g_y[(size_t)(b * 8 + j) * Cdim + h * 64 + d] = o / l_g;
}

// ---------------------------------------------------------------------------
// kernel_launch (single stream):
//   gemm_mma(qkv) -> reduce_qkv(q->g_q, kv->caches) -> attn_split ->
//   attn_combine -> gemm_mma(proj) -> reduce_proj
// ---------------------------------------------------------------------------
extern "C" void kernel_launch(void* const* d_in, const int* in_sizes, int n_in,
                              void* d_out, int out_size)
{
    const float* x      = (const float*)d_in[0];
    const float* past_k = (const float*)d_in[1];
    const float* past_v = (const float*)d_in[2];
    const float* W_attn = (const float*)d_in[3];
    const float* b_attn = (const float*)d_in[4];
    const float* W_proj = (const float*)d_in[5];
    const float* b_proj = (const float*)d_in[6];

    float* out  = (float*)d_out;
    float* kout = out + (size_t)NTOK * Cdim;
    float* vout = kout + (size_t)BHN * TFULL * HD;

    float* y_ptr  = nullptr;
    float* pp_ptr = nullptr;
    cudaGetSymbolAddress((void**)&y_ptr, g_y);
    cudaGetSymbolAddress((void**)&pp_ptr, g_part);

    static int init_done = 0;
    if (!init_done) {
        cudaFuncSetAttribute(attn_split,
            cudaFuncAttributeMaxDynamicSharedMemorySize, ATTN_SMEM);
        init_done = 1;
    }

    // 1) QKV projection via tf32 split-MMA (split-K, KC=128)
    gemm_mma_splitk<<<dim3(48, KSQ), 256>>>(x, W_attn, pp_ptr, 3072, 1024, 128);
    reduce_qkv<<<384, 256>>>(pp_ptr, b_attn, kout, vout);

    // 2) fused cache copy + pipelined split attention + combine
    attn_split<<<dim3(BHN, ASPLIT), 256, ATTN_SMEM>>>(past_k, past_v, kout, vout);
    attn_combine<<<BHN, 512>>>();

    // 3) output projection via tf32 split-MMA (split-K, KC=64)
    gemm_mma_splitk<<<dim3(16, KSP), 256>>>(y_ptr, W_proj, pp_ptr, 1024, 1024, 64);
    reduce_proj<<<128, 256>>>(pp_ptr, b_proj, out);
}